// round 1
// baseline (speedup 1.0000x reference)
#include <cuda_runtime.h>
#include <cstdint>

// ---------------------------------------------------------------------------
// Router gate: logits = H[16384,2048] @ W[64,2048]^T, affine cal, fp32 softmax,
// top-8 (probs, weights, indices-as-float).
// GEMM: fp32 via packed fma.rn.f32x2 (even/odd k in the two lanes).
// ---------------------------------------------------------------------------

#define T_TOKENS 16384
#define D_DIM    2048
#define E_EXP    64
#define TOPK     8
#define KC       32          // k-chunk (floats)
#define KP       (KC / 2)    // k-pairs per chunk
#define TILE_T   64          // tokens per CTA
#define STRIDE   36          // padded floats per smem row (144B, 16B aligned)
#define NCHUNK   (D_DIM / KC)
#define NTHREADS 128

typedef unsigned long long ull;

__device__ __forceinline__ unsigned sptr(const void* p) {
    return (unsigned)__cvta_generic_to_shared(p);
}

__device__ __forceinline__ void cp16(unsigned dst, const void* src) {
    asm volatile("cp.async.cg.shared.global [%0], [%1], 16;\n"
                 :: "r"(dst), "l"(src) : "memory");
}

__device__ __forceinline__ void cp_commit() {
    asm volatile("cp.async.commit_group;\n" ::: "memory");
}

template <int N>
__device__ __forceinline__ void cp_wait() {
    asm volatile("cp.async.wait_group %0;\n" :: "n"(N) : "memory");
}

// packed fp32x2 FMA: d.lo += a.lo*b.lo ; d.hi += a.hi*b.hi
__device__ __forceinline__ void ffma2(ull& d, ull a, ull b) {
    asm volatile("fma.rn.f32x2 %0, %1, %2, %0;\n"
                 : "+l"(d) : "l"(a), "l"(b));
}

__global__ void __launch_bounds__(NTHREADS)
router_gate_kernel(const float* __restrict__ gh,   // [T, D]
                   const float* __restrict__ gw,   // [E, D]
                   const float* __restrict__ gcs,  // [E]
                   const float* __restrict__ gcb,  // [E]
                   float* __restrict__ out,
                   int out_total)
{
    // smem: double-buffered h tile + double-buffered w tile.
    // logits region aliases the h region after the GEMM.
    __shared__ float smem[2 * TILE_T * STRIDE + 2 * E_EXP * STRIDE];
    float* hs = smem;                             // [2][64][36]
    float* ws = smem + 2 * TILE_T * STRIDE;       // [2][64][36]

    const int tid  = threadIdx.x;
    const int tok0 = blockIdx.x * TILE_T;
    const int tx   = tid & 15;    // token group (tokens tx + 16*i)
    const int ty   = tid >> 4;    // expert group (experts ty*8 .. ty*8+7)

    const unsigned hs_sh = sptr(hs);
    const unsigned ws_sh = sptr(ws);

    // ---------------- GEMM: 64 tokens x 64 experts, K = 2048 ----------------
    ull acc[4][8];
#pragma unroll
    for (int i = 0; i < 4; ++i)
#pragma unroll
        for (int j = 0; j < 8; ++j) acc[i][j] = 0ull;

    // tile loader: 64 rows x 32 floats for h and w, 16B chunks.
    // idx -> row = idx>>3, col = idx&7 : lanes 0..7 cover one contiguous row.
    auto load_tile = [&](int kb, int buf) {
        const float* hsrc = gh + (size_t)tok0 * D_DIM + kb * KC;
        const float* wsrc = gw + (size_t)kb * KC;
#pragma unroll
        for (int r = 0; r < 4; ++r) {
            int idx = tid + NTHREADS * r;
            int row = idx >> 3, col = idx & 7;
            unsigned doff = (unsigned)(((buf * TILE_T + row) * STRIDE + col * 4) * 4);
            cp16(hs_sh + doff, hsrc + (size_t)row * D_DIM + col * 4);
            cp16(ws_sh + doff, wsrc + (size_t)row * D_DIM + col * 4);
        }
        cp_commit();
    };

    load_tile(0, 0);

    const ull* hsu = reinterpret_cast<const ull*>(hs);
    const ull* wsu = reinterpret_cast<const ull*>(ws);

    for (int kb = 0; kb < NCHUNK; ++kb) {
        const int buf = kb & 1;
        if (kb + 1 < NCHUNK) {
            load_tile(kb + 1, buf ^ 1);
            cp_wait<1>();
        } else {
            cp_wait<0>();
        }
        __syncthreads();

        const ull* hb = hsu + (size_t)(buf * TILE_T) * (STRIDE / 2);
        const ull* wb = wsu + (size_t)(buf * E_EXP) * (STRIDE / 2);

#pragma unroll
        for (int k2 = 0; k2 < KP; ++k2) {
            ull h2[4], w2[8];
#pragma unroll
            for (int i = 0; i < 4; ++i)
                h2[i] = hb[(tx + 16 * i) * (STRIDE / 2) + k2];
#pragma unroll
            for (int j = 0; j < 8; ++j)
                w2[j] = wb[(ty * 8 + j) * (STRIDE / 2) + k2];
#pragma unroll
            for (int i = 0; i < 4; ++i)
#pragma unroll
                for (int j = 0; j < 8; ++j)
                    ffma2(acc[i][j], h2[i], w2[j]);
        }
        __syncthreads();
    }

    // ---------------- raw logits -> smem (alias h region) --------------------
    float* lg = smem;  // [64][65]
#pragma unroll
    for (int i = 0; i < 4; ++i)
#pragma unroll
        for (int j = 0; j < 8; ++j) {
            float2 v = *reinterpret_cast<float2*>(&acc[i][j]);
            lg[(tx + 16 * i) * 65 + (ty * 8 + j)] = v.x + v.y;
        }
    __syncthreads();

    // ---------------- warp-per-token: softmax + top-8 ------------------------
    const int lane = tid & 31;
    const int warp = tid >> 5;

    const float s0 = gcs[lane], s1 = gcs[lane + 32];
    const float b0 = gcb[lane], b1 = gcb[lane + 32];

    float* probs_out = out;
    float* w_out = out + (size_t)T_TOKENS * E_EXP;
    float* i_out = w_out + (size_t)T_TOKENS * TOPK;
    const bool has_extra =
        out_total >= (int)(T_TOKENS * E_EXP + 2 * T_TOKENS * TOPK);

    for (int t = 0; t < TILE_T / 4; ++t) {
        const int ltok = warp * (TILE_T / 4) + t;
        const size_t gtok = (size_t)(tok0 + ltok);

        // calibrated logits (lane owns experts {lane, lane+32})
        float l0 = lg[ltok * 65 + lane]      * s0 + b0;
        float l1 = lg[ltok * 65 + lane + 32] * s1 + b1;

        // exact max reduce
        float m = fmaxf(l0, l1);
#pragma unroll
        for (int off = 16; off; off >>= 1)
            m = fmaxf(m, __shfl_xor_sync(0xffffffffu, m, off));

        float p0 = expf(l0 - m);
        float p1 = expf(l1 - m);
        float s = p0 + p1;
#pragma unroll
        for (int off = 16; off; off >>= 1)
            s += __shfl_xor_sync(0xffffffffu, s, off);

        float q0 = p0 / s;
        float q1 = p1 / s;

        probs_out[gtok * E_EXP + lane]      = q0;
        probs_out[gtok * E_EXP + lane + 32] = q1;

        // top-8 with lowest-index tie-break (matches jax.lax.top_k)
        float v0 = q0, v1 = q1;
        float keepw = 0.0f;
        int keepi = 0;
#pragma unroll
        for (int pass = 0; pass < TOPK; ++pass) {
            bool sel1 = v1 > v0;               // tie -> lower index (v0)
            float cv = sel1 ? v1 : v0;
            int   ci = sel1 ? (lane + 32) : lane;
#pragma unroll
            for (int off = 16; off; off >>= 1) {
                float ov = __shfl_xor_sync(0xffffffffu, cv, off);
                int   oi = __shfl_xor_sync(0xffffffffu, ci, off);
                if (ov > cv || (ov == cv && oi < ci)) { cv = ov; ci = oi; }
            }
            if (lane == pass) { keepw = cv; keepi = ci; }
            if (ci == lane)      v0 = -1.0f;
            if (ci == lane + 32) v1 = -1.0f;
        }
        if (has_extra && lane < TOPK) {
            w_out[gtok * TOPK + lane] = keepw;
            i_out[gtok * TOPK + lane] = (float)keepi;
        }
    }
}

extern "C" void kernel_launch(void* const* d_in, const int* in_sizes, int n_in,
                              void* d_out, int out_size) {
    const float* h  = (const float*)d_in[0];  // hidden_states [4,4096,2048] f32
    const float* w  = (const float*)d_in[1];  // router_weight [64,2048] f32
    const float* cs = (const float*)d_in[2];  // cal_scale [64] f32
    const float* cb = (const float*)d_in[3];  // cal_bias  [64] f32
    (void)in_sizes; (void)n_in;

    router_gate_kernel<<<T_TOKENS / TILE_T, NTHREADS>>>(
        h, w, cs, cb, (float*)d_out, out_size);
}

// round 3
// speedup vs baseline: 1.0323x; 1.0323x over previous
#include <cuda_runtime.h>
#include <cstdint>

// ---------------------------------------------------------------------------
// Router gate: logits = H[16384,2048] @ W[64,2048]^T, affine cal, fp32 softmax,
// top-8 (probs, weights, indices-as-float).
// GEMM: fp32 via packed fma.rn.f32x2. R2/R3: 32-token tiles (512 CTAs, one
// full wave), 3-stage cp.async pipeline, single barrier per k-chunk.
// (R3 = R2 resubmitted: round-2 bench was an infra failure, kernel never ran.)
// ---------------------------------------------------------------------------

#define T_TOKENS 16384
#define D_DIM    2048
#define E_EXP    64
#define TOPK     8
#define KC       32          // k-chunk (floats)
#define KP       (KC / 2)    // k-pairs per chunk
#define TILE_T   32          // tokens per CTA
#define STRIDE   36          // padded floats per smem row (144B, 16B aligned)
#define NCHUNK   (D_DIM / KC)
#define NSTAGE   3
#define NTHREADS 128

typedef unsigned long long ull;

__device__ __forceinline__ unsigned sptr(const void* p) {
    return (unsigned)__cvta_generic_to_shared(p);
}

__device__ __forceinline__ void cp16(unsigned dst, const void* src) {
    asm volatile("cp.async.cg.shared.global [%0], [%1], 16;\n"
                 :: "r"(dst), "l"(src) : "memory");
}

__device__ __forceinline__ void cp_commit() {
    asm volatile("cp.async.commit_group;\n" ::: "memory");
}

template <int N>
__device__ __forceinline__ void cp_wait() {
    asm volatile("cp.async.wait_group %0;\n" :: "n"(N) : "memory");
}

// packed fp32x2 FMA: d.lo += a.lo*b.lo ; d.hi += a.hi*b.hi
__device__ __forceinline__ void ffma2(ull& d, ull a, ull b) {
    asm volatile("fma.rn.f32x2 %0, %1, %2, %0;\n"
                 : "+l"(d) : "l"(a), "l"(b));
}

__global__ void __launch_bounds__(NTHREADS, 4)
router_gate_kernel(const float* __restrict__ gh,   // [T, D]
                   const float* __restrict__ gw,   // [E, D]
                   const float* __restrict__ gcs,  // [E]
                   const float* __restrict__ gcb,  // [E]
                   float* __restrict__ out,
                   int out_total)
{
    // 3-stage h tiles + 3-stage w tiles; logits alias the front after GEMM.
    __shared__ float smem[NSTAGE * TILE_T * STRIDE + NSTAGE * E_EXP * STRIDE];
    float* hs = smem;                                      // [3][32][36]
    float* ws = smem + NSTAGE * TILE_T * STRIDE;           // [3][64][36]

    const int tid  = threadIdx.x;
    const int tok0 = blockIdx.x * TILE_T;
    const int tx   = tid & 7;     // token group  (tokens tx + 8*i)
    const int ty   = tid >> 3;    // expert group (experts ty*4 .. ty*4+3)

    const unsigned hs_sh = sptr(hs);
    const unsigned ws_sh = sptr(ws);

    // ---------------- GEMM: 32 tokens x 64 experts, K = 2048 ----------------
    ull acc[4][4];
#pragma unroll
    for (int i = 0; i < 4; ++i)
#pragma unroll
        for (int j = 0; j < 4; ++j) acc[i][j] = 0ull;

    // stage loader: h 32x32 floats (256 x 16B), w 64x32 floats (512 x 16B)
    auto load_tile = [&](int kb, int s) {
        const float* hsrc = gh + (size_t)tok0 * D_DIM + kb * KC;
        const float* wsrc = gw + (size_t)kb * KC;
#pragma unroll
        for (int r = 0; r < 2; ++r) {
            int idx = tid + NTHREADS * r;
            int row = idx >> 3, col = idx & 7;
            unsigned doff = (unsigned)(((s * TILE_T + row) * STRIDE + col * 4) * 4);
            cp16(hs_sh + doff, hsrc + (size_t)row * D_DIM + col * 4);
        }
#pragma unroll
        for (int r = 0; r < 4; ++r) {
            int idx = tid + NTHREADS * r;
            int row = idx >> 3, col = idx & 7;
            unsigned doff = (unsigned)(((s * E_EXP + row) * STRIDE + col * 4) * 4);
            cp16(ws_sh + doff, wsrc + (size_t)row * D_DIM + col * 4);
        }
        cp_commit();
    };

    load_tile(0, 0);
    load_tile(1, 1);

    const ull* hsu = reinterpret_cast<const ull*>(hs);
    const ull* wsu = reinterpret_cast<const ull*>(ws);

    int s_next = 2;   // stage that load(kb+2) targets
    for (int kb = 0; kb < NCHUNK; ++kb) {
        // make stage kb visible (groups kb..kb+1 may be in flight)
        if (kb + 1 < NCHUNK) cp_wait<1>(); else cp_wait<0>();
        __syncthreads();   // also proves compute(kb-1) done -> stage free

        if (kb + 2 < NCHUNK) {
            load_tile(kb + 2, s_next);
            if (++s_next == NSTAGE) s_next = 0;
        }

        const int s = kb % NSTAGE;
        const ull* hb = hsu + (size_t)(s * TILE_T) * (STRIDE / 2);
        const ull* wb = wsu + (size_t)(s * E_EXP) * (STRIDE / 2);

#pragma unroll
        for (int k2 = 0; k2 < KP; ++k2) {
            ull h2[4], w2[4];
#pragma unroll
            for (int i = 0; i < 4; ++i)
                h2[i] = hb[(tx + 8 * i) * (STRIDE / 2) + k2];
#pragma unroll
            for (int j = 0; j < 4; ++j)
                w2[j] = wb[(ty * 4 + j) * (STRIDE / 2) + k2];
#pragma unroll
            for (int i = 0; i < 4; ++i)
#pragma unroll
                for (int j = 0; j < 4; ++j)
                    ffma2(acc[i][j], h2[i], w2[j]);
        }
    }
    __syncthreads();   // all stages done; smem reusable for logits

    // ---------------- raw logits -> smem ------------------------------------
    float* lg = smem;  // [32][65]
#pragma unroll
    for (int i = 0; i < 4; ++i)
#pragma unroll
        for (int j = 0; j < 4; ++j) {
            float2 v = *reinterpret_cast<float2*>(&acc[i][j]);
            lg[(tx + 8 * i) * 65 + (ty * 4 + j)] = v.x + v.y;
        }
    __syncthreads();

    // ---------------- warp-per-token: softmax + top-8 ------------------------
    const int lane = tid & 31;
    const int warp = tid >> 5;

    const float s0 = gcs[lane], s1 = gcs[lane + 32];
    const float b0 = gcb[lane], b1 = gcb[lane + 32];

    float* probs_out = out;
    float* w_out = out + (size_t)T_TOKENS * E_EXP;
    float* i_out = w_out + (size_t)T_TOKENS * TOPK;
    const bool has_extra =
        out_total >= (int)(T_TOKENS * E_EXP + 2 * T_TOKENS * TOPK);

    for (int t = 0; t < TILE_T / 4; ++t) {
        const int ltok = warp * (TILE_T / 4) + t;
        const size_t gtok = (size_t)(tok0 + ltok);

        // calibrated logits (lane owns experts {lane, lane+32})
        float l0 = lg[ltok * 65 + lane]      * s0 + b0;
        float l1 = lg[ltok * 65 + lane + 32] * s1 + b1;

        // exact max reduce
        float m = fmaxf(l0, l1);
#pragma unroll
        for (int off = 16; off; off >>= 1)
            m = fmaxf(m, __shfl_xor_sync(0xffffffffu, m, off));

        float p0 = expf(l0 - m);
        float p1 = expf(l1 - m);
        float s = p0 + p1;
#pragma unroll
        for (int off = 16; off; off >>= 1)
            s += __shfl_xor_sync(0xffffffffu, s, off);

        float q0 = p0 / s;
        float q1 = p1 / s;

        probs_out[gtok * E_EXP + lane]      = q0;
        probs_out[gtok * E_EXP + lane + 32] = q1;

        // top-8 with lowest-index tie-break (matches jax.lax.top_k)
        float v0 = q0, v1 = q1;
        float keepw = 0.0f;
        int keepi = 0;
#pragma unroll
        for (int pass = 0; pass < TOPK; ++pass) {
            bool sel1 = v1 > v0;               // tie -> lower index (v0)
            float cv = sel1 ? v1 : v0;
            int   ci = sel1 ? (lane + 32) : lane;
#pragma unroll
            for (int off = 16; off; off >>= 1) {
                float ov = __shfl_xor_sync(0xffffffffu, cv, off);
                int   oi = __shfl_xor_sync(0xffffffffu, ci, off);
                if (ov > cv || (ov == cv && oi < ci)) { cv = ov; ci = oi; }
            }
            if (lane == pass) { keepw = cv; keepi = ci; }
            if (ci == lane)      v0 = -1.0f;
            if (ci == lane + 32) v1 = -1.0f;
        }
        if (has_extra && lane < TOPK) {
            w_out[gtok * TOPK + lane] = keepw;
            i_out[gtok * TOPK + lane] = (float)keepi;
        }
    }
}

extern "C" void kernel_launch(void* const* d_in, const int* in_sizes, int n_in,
                              void* d_out, int out_size) {
    const float* h  = (const float*)d_in[0];  // hidden_states [4,4096,2048] f32
    const float* w  = (const float*)d_in[1];  // router_weight [64,2048] f32
    const float* cs = (const float*)d_in[2];  // cal_scale [64] f32
    const float* cb = (const float*)d_in[3];  // cal_bias  [64] f32
    (void)in_sizes; (void)n_in;

    router_gate_kernel<<<T_TOKENS / TILE_T, NTHREADS>>>(
        h, w, cs, cb, (float*)d_out, out_size);
}

// round 11
// speedup vs baseline: 1.0367x; 1.0043x over previous
#include <cuda_runtime.h>
#include <cstdint>

// ---------------------------------------------------------------------------
// Router gate, FFMA2 (fp32 f32x2) GEMM — bitwise-identical per-logit chain to
// the R1/R3 kernels that PASSED (rel_err 3.2e-4): one f32x2 accumulator per
// logit, sequential k-pairs 0..1023, final lo+hi. This round only changes the
// data movement: 8tx x 4ty warp layout (4/8-way LDS broadcast), LDS.128
// double-k loads, XOR-swizzled W smem ([k4][e^ty]) for conflict-free reads.
// R3 was LDS-wavefront-bound (L1 64.6%, fma 42%); this halves LDS pressure.
// ---------------------------------------------------------------------------

#define T_TOKENS 16384
#define D_DIM    2048
#define E_EXP    64
#define TOPK     8
#define TILE_T   128
#define KC       32                    // floats per k-chunk
#define NCHUNK   (D_DIM / KC)          // 64
#define NTHREADS 256

// stage layout (words): H[128][36] | W[8 k4][64 e][4]
#define H_WORDS     (128 * 36)         // 4608
#define W_WORDS     (8 * 64 * 4)       // 2048
#define STAGE_WORDS (H_WORDS + W_WORDS)// 6656
#define SMEM_BYTES  (2 * STAGE_WORDS * 4)  // 53248

typedef unsigned long long ull;
struct ull2 { ull x, y; };

__device__ __forceinline__ unsigned sptr(const void* p) {
    return (unsigned)__cvta_generic_to_shared(p);
}
__device__ __forceinline__ void cp16(unsigned dst, const void* src) {
    asm volatile("cp.async.cg.shared.global [%0], [%1], 16;\n"
                 :: "r"(dst), "l"(src) : "memory");
}
__device__ __forceinline__ void cp_commit() {
    asm volatile("cp.async.commit_group;\n" ::: "memory");
}
template <int N>
__device__ __forceinline__ void cp_wait() {
    asm volatile("cp.async.wait_group %0;\n" :: "n"(N) : "memory");
}

// packed fp32x2 FMA: d.lo += a.lo*b.lo ; d.hi += a.hi*b.hi  (same as R1/R3)
__device__ __forceinline__ void ffma2(ull& d, ull a, ull b) {
    asm volatile("fma.rn.f32x2 %0, %1, %2, %0;\n"
                 : "+l"(d) : "l"(a), "l"(b));
}

__device__ __forceinline__ ull2 lds128(const void* p) {
    ull2 r;
    unsigned a = sptr(p);
    asm volatile("ld.shared.v2.u64 {%0, %1}, [%2];\n"
                 : "=l"(r.x), "=l"(r.y) : "r"(a));
    return r;
}

extern __shared__ float smemf[];

__global__ void __launch_bounds__(NTHREADS, 1)
router_gate_f2(const float* __restrict__ gh,   // [T, D]
               const float* __restrict__ gw,   // [E, D]
               const float* __restrict__ gcs,  // [E]
               const float* __restrict__ gcb,  // [E]
               float* __restrict__ out,
               int out_total)
{
    const int tid    = threadIdx.x;
    const int wid    = tid >> 5;
    const int lane   = tid & 31;
    const int warp_m = wid & 3;        // token group: rows [warp_m*32, +32)
    const int warp_n = wid >> 2;       // expert half: cols [warp_n*32, +32)
    const int tx     = lane & 7;       // token-in-group (tokens tx + 8i)
    const int ty     = lane >> 3;      // expert subgroup (experts ty*8 + j)
    const int tok0   = blockIdx.x * TILE_T;

    const unsigned smem_sh = sptr(smemf);
    const float* hbase = gh + (size_t)tok0 * D_DIM;

    // ---- producers (both plain fp32 copies via cp.async) ---------------
    auto load_stage = [&](int kb, int s) {
        const float* hsrc = hbase + kb * KC;
#pragma unroll
        for (int it = 0; it < 4; ++it) {
            int idx = tid + NTHREADS * it;       // 0..1023
            int row = idx >> 3, c4 = idx & 7;
            unsigned doff = (unsigned)((s * STAGE_WORDS + row * 36 + c4 * 4) * 4);
            cp16(smem_sh + doff, hsrc + (size_t)row * D_DIM + c4 * 4);
        }
        const float* wsrc = gw + kb * KC;
#pragma unroll
        for (int it = 0; it < 2; ++it) {
            int idx = tid + NTHREADS * it;       // 0..511
            int e = idx >> 3, k4 = idx & 7;
            int es = e ^ ((e >> 3) & 3);         // XOR swizzle: kills 4-way ty conflict
            unsigned doff = (unsigned)((s * STAGE_WORDS + H_WORDS +
                                        (k4 * 64 + es) * 4) * 4);
            cp16(smem_sh + doff, wsrc + (size_t)e * D_DIM + k4 * 4);
        }
        cp_commit();
    };

    // ---- prologue ------------------------------------------------------
    load_stage(0, 0);

    ull acc[4][8];
#pragma unroll
    for (int i = 0; i < 4; ++i)
#pragma unroll
        for (int j = 0; j < 8; ++j) acc[i][j] = 0ull;

    // per-thread byte offsets
    const char* smemc = reinterpret_cast<const char*>(smemf);
    int hoff[4];
#pragma unroll
    for (int i = 0; i < 4; ++i)
        hoff[i] = (warp_m * 32 + tx + 8 * i) * 144;   // row * 36 words * 4B
    int woff[8];
#pragma unroll
    for (int j = 0; j < 8; ++j)
        woff[j] = (warp_n * 32 + ty * 8 + (j ^ ty)) * 16;  // swizzled slot

    // ---- mainloop ------------------------------------------------------
    for (int kb = 0; kb < NCHUNK; ++kb) {
        const int s = kb & 1;
        cp_wait<0>();
        __syncthreads();                 // stage s ready; s^1 free

        if (kb + 1 < NCHUNK) load_stage(kb + 1, s ^ 1);

        const char* hs = smemc + (size_t)s * STAGE_WORDS * 4;
        const char* ws = hs + H_WORDS * 4;

#pragma unroll
        for (int k4 = 0; k4 < 8; ++k4) {
            ull2 hv[4];
#pragma unroll
            for (int i = 0; i < 4; ++i)
                hv[i] = lds128(hs + hoff[i] + k4 * 16);

#pragma unroll
            for (int jb = 0; jb < 2; ++jb) {
                ull2 wv[4];
#pragma unroll
                for (int jj = 0; jj < 4; ++jj)
                    wv[jj] = lds128(ws + k4 * 1024 + woff[jb * 4 + jj]);
#pragma unroll
                for (int i = 0; i < 4; ++i)
#pragma unroll
                    for (int jj = 0; jj < 4; ++jj) {
                        // sequential k2 order per accumulator (bitwise = R3)
                        ffma2(acc[i][jb * 4 + jj], hv[i].x, wv[jj].x);
                        ffma2(acc[i][jb * 4 + jj], hv[i].y, wv[jj].y);
                    }
            }
        }
    }
    __syncthreads();   // all consumers done; smem reusable for logits

    // ---- raw logits -> smem [128][65] (lo+hi, same as R3) ---------------
    float* lg = smemf;
#pragma unroll
    for (int i = 0; i < 4; ++i)
#pragma unroll
        for (int j = 0; j < 8; ++j) {
            float2 v = *reinterpret_cast<float2*>(&acc[i][j]);
            int row = warp_m * 32 + tx + 8 * i;
            int col = warp_n * 32 + ty * 8 + j;
            lg[row * 65 + col] = v.x + v.y;
        }
    __syncthreads();

    // ---- warp-per-token softmax + top-8 (verbatim from R3) --------------
    const float s0 = gcs[lane], s1 = gcs[lane + 32];
    const float b0 = gcb[lane], b1 = gcb[lane + 32];

    float* probs_out = out;
    float* w_out = out + (size_t)T_TOKENS * E_EXP;
    float* i_out = w_out + (size_t)T_TOKENS * TOPK;
    const bool has_extra =
        out_total >= (int)(T_TOKENS * E_EXP + 2 * T_TOKENS * TOPK);

    for (int tt = 0; tt < TILE_T / 8; ++tt) {
        const int ltok = wid * (TILE_T / 8) + tt;
        const size_t gtok = (size_t)(tok0 + ltok);

        float l0 = lg[ltok * 65 + lane]      * s0 + b0;
        float l1 = lg[ltok * 65 + lane + 32] * s1 + b1;

        float m = fmaxf(l0, l1);
#pragma unroll
        for (int off = 16; off; off >>= 1)
            m = fmaxf(m, __shfl_xor_sync(0xffffffffu, m, off));

        float p0 = expf(l0 - m);
        float p1 = expf(l1 - m);
        float sm = p0 + p1;
#pragma unroll
        for (int off = 16; off; off >>= 1)
            sm += __shfl_xor_sync(0xffffffffu, sm, off);

        float q0 = p0 / sm;
        float q1 = p1 / sm;

        probs_out[gtok * E_EXP + lane]      = q0;
        probs_out[gtok * E_EXP + lane + 32] = q1;

        float v0 = q0, v1 = q1;
        float keepw = 0.0f;
        int keepi = 0;
#pragma unroll
        for (int pass = 0; pass < TOPK; ++pass) {
            bool sel1 = v1 > v0;               // tie -> lower index
            float cv = sel1 ? v1 : v0;
            int   ci = sel1 ? (lane + 32) : lane;
#pragma unroll
            for (int off = 16; off; off >>= 1) {
                float ov = __shfl_xor_sync(0xffffffffu, cv, off);
                int   oi = __shfl_xor_sync(0xffffffffu, ci, off);
                if (ov > cv || (ov == cv && oi < ci)) { cv = ov; ci = oi; }
            }
            if (lane == pass) { keepw = cv; keepi = ci; }
            if (ci == lane)      v0 = -1.0f;
            if (ci == lane + 32) v1 = -1.0f;
        }
        if (has_extra && lane < TOPK) {
            w_out[gtok * TOPK + lane] = keepw;
            i_out[gtok * TOPK + lane] = (float)keepi;
        }
    }
}

extern "C" void kernel_launch(void* const* d_in, const int* in_sizes, int n_in,
                              void* d_out, int out_size) {
    const float* h  = (const float*)d_in[0];  // hidden_states [4,4096,2048] f32
    const float* w  = (const float*)d_in[1];  // router_weight [64,2048] f32
    const float* cs = (const float*)d_in[2];  // cal_scale [64]
    const float* cb = (const float*)d_in[3];  // cal_bias  [64]
    (void)in_sizes; (void)n_in;

    cudaFuncSetAttribute(router_gate_f2,
                         cudaFuncAttributeMaxDynamicSharedMemorySize,
                         SMEM_BYTES);
    router_gate_f2<<<T_TOKENS / TILE_T, NTHREADS, SMEM_BYTES>>>(
        h, w, cs, cb, (float*)d_out, out_size);
}